// round 6
// baseline (speedup 1.0000x reference)
#include <cuda_runtime.h>

#define N_NODES 100000
#define E_REAL  3200000
#define E_TOT   3300000
#define IN_CH   256
#define HID     64
#define HEADS1  8
#define OUT_CH  3
#define CNT_PAD 100352   // 196 * 512

typedef unsigned long long ull;

// ---------------- scratch (static device globals; no runtime alloc) ----------------
__device__ int   d_is64;                  // 1 if edge_index is int64, 0 if int32
__device__ int   d_cnt[CNT_PAD];          // degree counts -> scatter cursors
__device__ int   d_rowptr[N_NODES + 1];
__device__ int   d_part[256];             // scan partials
__device__ __align__(16) int d_col[E_TOT];   // CSR: src per (dst-sorted) edge
__device__ __align__(16) float  d_h1[N_NODES * HID];
__device__ __align__(16) float  d_as1[N_NODES * HEADS1];
__device__ __align__(16) float  d_ad1[N_NODES * HEADS1];
__device__ __align__(16) float  d_hmid[N_NODES * HID];   // elu(gat1 + b1)
__device__ __align__(16) float4 d_h2p[N_NODES];          // {h2[0..2], as2}
__device__ __align__(16) float  d_ad2[N_NODES];

// ---------------- f32x2 packed helpers ----------------
__device__ __forceinline__ void fma2(ull& d, ull a, ull b) {
    asm("fma.rn.f32x2 %0, %1, %2, %0;" : "+l"(d) : "l"(a), "l"(b));
}
__device__ __forceinline__ ull pack2(float lo, float hi) {
    ull r; asm("mov.b64 %0, {%1, %2};" : "=l"(r) : "f"(lo), "f"(hi)); return r;
}
__device__ __forceinline__ float2 unpack2(ull v) {
    float2 r; asm("mov.b64 {%0, %1}, %2;" : "=f"(r.x), "=f"(r.y) : "l"(v)); return r;
}

// Decode edge endpoint i (0..E_REAL-1); which=0 -> src row, which=1 -> dst row.
__device__ __forceinline__ int edge_at(const void* ei, int which, int i) {
    if (d_is64) {
        const long long* p = (const long long*)ei;
        return (int)p[(size_t)which * E_REAL + i];
    } else {
        const int* p = (const int*)ei;
        return p[(size_t)which * E_REAL + i];
    }
}

// ---------------- dtype probe ----------------
__global__ void k_detect(const int* __restrict__ ei32) {
    __shared__ int nz;
    if (threadIdx.x == 0) nz = 0;
    __syncthreads();
    if (ei32[2 * threadIdx.x + 1] != 0) atomicOr(&nz, 1);
    __syncthreads();
    if (threadIdx.x == 0) d_is64 = (nz == 0) ? 1 : 0;
}

// ---------------- CSR build ----------------
__global__ void k_init() {
    int i = blockIdx.x * blockDim.x + threadIdx.x;
    if (i < CNT_PAD) d_cnt[i] = (i < N_NODES) ? 1 : 0;   // 1 = self loop
}

__global__ void k_hist(const void* __restrict__ ei) {
    int i = blockIdx.x * blockDim.x + threadIdx.x;
    if (i < E_REAL) {
        int d = edge_at(ei, 1, i);
        if ((unsigned)d < N_NODES) atomicAdd(&d_cnt[d], 1);
    }
}

__global__ void k_scan_part() {            // 196 blocks x 256 thr
    __shared__ int s[256];
    int b = blockIdx.x, t = threadIdx.x;
    int i0 = b * 512 + t;
    int v = d_cnt[i0] + d_cnt[i0 + 256];
    s[t] = v; __syncthreads();
    for (int off = 128; off > 0; off >>= 1) {
        if (t < off) s[t] += s[t + off];
        __syncthreads();
    }
    if (t == 0) d_part[b] = s[0];
}

__global__ void k_scan_top() {             // 1 block x 256 thr
    __shared__ int s[256];
    int t = threadIdx.x;
    int v = (t < 196) ? d_part[t] : 0;
    s[t] = v; __syncthreads();
    for (int off = 1; off < 256; off <<= 1) {
        int x = (t >= off) ? s[t - off] : 0;
        __syncthreads();
        s[t] += x;
        __syncthreads();
    }
    if (t < 196) d_part[t] = s[t] - v;     // exclusive
}

__global__ void k_scan_chunk() {           // 196 blocks x 512 thr
    __shared__ int s[512];
    int b = blockIdx.x, t = threadIdx.x;
    int i = b * 512 + t;
    int v = d_cnt[i];
    s[t] = v; __syncthreads();
    for (int off = 1; off < 512; off <<= 1) {
        int x = (t >= off) ? s[t - off] : 0;
        __syncthreads();
        s[t] += x;
        __syncthreads();
    }
    if (i <= N_NODES) d_rowptr[i] = d_part[b] + s[t] - v;
}

__global__ void k_selfloop() {
    int i = blockIdx.x * blockDim.x + threadIdx.x;
    if (i < N_NODES) {
        int p = d_rowptr[i];
        d_col[p] = i;          // self loop first
        d_cnt[i] = p + 1;      // cursor
    }
}

__global__ void k_scatter(const void* __restrict__ ei) {
    int i = blockIdx.x * blockDim.x + threadIdx.x;
    if (i < E_REAL) {
        int s = edge_at(ei, 0, i);
        int d = edge_at(ei, 1, i);
        if ((unsigned)d < N_NODES && (unsigned)s < N_NODES) {
            int p = atomicAdd(&d_cnt[d], 1);
            d_col[p] = s;
        }
    }
}

// ---------------- GEMM1 + fused alpha1 ----------------
// h1 = x @ W1 (100000x256 @ 256x64). Tile: 128 rows x 64 cols, 256 threads,
// 4x8 per thread via packed f32x2 FMA (acc = 16 ull = 32 regs -> 3 blocks/SM).
// Thread (tx,ty): cols tx*8..+7 (head tx), rows row0+ty*4..+3 (2 row-pairs).
// Epilogue: fp32 h1 rows + fused as1/ad1 for head tx.
__global__ void __launch_bounds__(256, 3) k_gemm1(const float* __restrict__ x,
                                                  const float* __restrict__ W,
                                                  const float* __restrict__ a_src,
                                                  const float* __restrict__ a_dst) {
    __shared__ float xs[32][132];   // [k][row], pad 4: 16B-aligned rows
    __shared__ float ws[32][64];    // [k][col]
    int t = threadIdx.x;
    int tx = t & 7, ty = t >> 3;    // tx: col group (head), ty: row group 0..31
    int row0 = blockIdx.x * 128;
    ull acc[2][8];                  // [rowpair][col]
    #pragma unroll
    for (int i = 0; i < 2; i++)
        #pragma unroll
        for (int j = 0; j < 8; j++) acc[i][j] = 0ull;

    for (int k0 = 0; k0 < IN_CH; k0 += 32) {
        #pragma unroll
        for (int j = 0; j < 4; j++) {            // x tile: 1024 float4
            int f4 = t + 256 * j;
            int r = f4 >> 3, k4 = f4 & 7;
            int grow = row0 + r;
            float4 v = (grow < N_NODES)
                ? *(const float4*)(x + (size_t)grow * IN_CH + k0 + k4 * 4)
                : make_float4(0.f, 0.f, 0.f, 0.f);
            xs[k4 * 4 + 0][r] = v.x; xs[k4 * 4 + 1][r] = v.y;
            xs[k4 * 4 + 2][r] = v.z; xs[k4 * 4 + 3][r] = v.w;
        }
        #pragma unroll
        for (int j = 0; j < 2; j++) {            // W tile: 512 float4
            int f4 = t + 256 * j;
            int kk = f4 >> 4, c4 = f4 & 15;
            *(float4*)&ws[kk][c4 * 4] = *(const float4*)(W + (k0 + kk) * HID + c4 * 4);
        }
        __syncthreads();
        #pragma unroll
        for (int kk = 0; kk < 32; kk++) {
            // 4 consecutive x rows as 2 packed f32x2 (natural pairs, no packs)
            ulonglong2 xa = *(const ulonglong2*)&xs[kk][ty * 4];
            ull xr[2] = { xa.x, xa.y };
            const float4* wr = (const float4*)&ws[kk][tx * 8];
            float4 wv0 = wr[0], wv1 = wr[1];
            ull wp[8] = { pack2(wv0.x, wv0.x), pack2(wv0.y, wv0.y),
                          pack2(wv0.z, wv0.z), pack2(wv0.w, wv0.w),
                          pack2(wv1.x, wv1.x), pack2(wv1.y, wv1.y),
                          pack2(wv1.z, wv1.z), pack2(wv1.w, wv1.w) };
            #pragma unroll
            for (int rp = 0; rp < 2; rp++)
                #pragma unroll
                for (int c = 0; c < 8; c++)
                    fma2(acc[rp][c], xr[rp], wp[c]);
        }
        __syncthreads();
    }

    // epilogue: fp32 h1 rows + fused attention alphas for head tx
    float sa[8], sd[8];
    #pragma unroll
    for (int c = 0; c < 8; c++) {
        sa[c] = __ldg(a_src + tx * 8 + c);
        sd[c] = __ldg(a_dst + tx * 8 + c);
    }
    #pragma unroll
    for (int rp = 0; rp < 2; rp++) {
        float lo[8], hi[8];
        #pragma unroll
        for (int c = 0; c < 8; c++) {
            float2 u = unpack2(acc[rp][c]);
            lo[c] = u.x; hi[c] = u.y;
        }
        int rA = row0 + ty * 4 + rp * 2;
        if (rA < N_NODES) {
            float* hp = d_h1 + (size_t)rA * HID + tx * 8;
            *(float4*)hp       = make_float4(lo[0], lo[1], lo[2], lo[3]);
            *(float4*)(hp + 4) = make_float4(lo[4], lo[5], lo[6], lo[7]);
            float as = 0.f, ad = 0.f;
            #pragma unroll
            for (int c = 0; c < 8; c++) { as = fmaf(lo[c], sa[c], as); ad = fmaf(lo[c], sd[c], ad); }
            d_as1[rA * HEADS1 + tx] = as;
            d_ad1[rA * HEADS1 + tx] = ad;
        }
        int rB = rA + 1;
        if (rB < N_NODES) {
            float* hp = d_h1 + (size_t)rB * HID + tx * 8;
            *(float4*)hp       = make_float4(hi[0], hi[1], hi[2], hi[3]);
            *(float4*)(hp + 4) = make_float4(hi[4], hi[5], hi[6], hi[7]);
            float as = 0.f, ad = 0.f;
            #pragma unroll
            for (int c = 0; c < 8; c++) { as = fmaf(hi[c], sa[c], as); ad = fmaf(hi[c], sd[c], ad); }
            d_as1[rB * HEADS1 + tx] = as;
            d_ad1[rB * HEADS1 + tx] = ad;
        }
    }
}

// ---------------- GAT pull layer 1: warp per dst node, lane owns 2 channels ----------------
// Each lane walks ALL edges of its node (full per-lane wsum; no reduction).
// col[] consumed via int4: 1 uniform LDG.128 per 4 edges (cuts warp LDG count 25%).
__global__ void __launch_bounds__(128) k_pull1(const float* __restrict__ b1) {
    int n = blockIdx.x * 4 + (threadIdx.x >> 5);
    if (n >= N_NODES) return;
    int lane = threadIdx.x & 31;
    int c2 = lane * 2;
    int hd = lane >> 2;              // 4 lanes per head
    float adv = d_ad1[n * HEADS1 + hd];
    int e0 = d_rowptr[n], e1 = d_rowptr[n + 1];
    float ax = 0.f, ay = 0.f, wsum = 0.f;

    int e = e0;
    int ehead = (e0 + 3) & ~3;       // align up to 4
    if (ehead > e1) ehead = e1;
    for (; e < ehead; e++) {         // unaligned head
        int s = __ldg(&d_col[e]);
        float al = __ldg(&d_as1[s * HEADS1 + hd]) + adv;
        al = al > 0.f ? al : 0.2f * al;
        float w = __expf(al);
        float2 hv = *(const float2*)(d_h1 + (size_t)s * HID + c2);
        ax = fmaf(w, hv.x, ax); ay = fmaf(w, hv.y, ay);
        wsum += w;
    }
    for (; e + 4 <= e1; e += 4) {    // aligned body: one LDG.128 for 4 src ids
        int4 c4 = *(const int4*)&d_col[e];
        float g0 = __ldg(&d_as1[c4.x * HEADS1 + hd]);
        float g1 = __ldg(&d_as1[c4.y * HEADS1 + hd]);
        float g2 = __ldg(&d_as1[c4.z * HEADS1 + hd]);
        float g3 = __ldg(&d_as1[c4.w * HEADS1 + hd]);
        float2 h0 = *(const float2*)(d_h1 + (size_t)c4.x * HID + c2);
        float2 h1v = *(const float2*)(d_h1 + (size_t)c4.y * HID + c2);
        float2 h2v = *(const float2*)(d_h1 + (size_t)c4.z * HID + c2);
        float2 h3 = *(const float2*)(d_h1 + (size_t)c4.w * HID + c2);
        float a0 = g0 + adv; a0 = a0 > 0.f ? a0 : 0.2f * a0;
        float a1 = g1 + adv; a1 = a1 > 0.f ? a1 : 0.2f * a1;
        float a2 = g2 + adv; a2 = a2 > 0.f ? a2 : 0.2f * a2;
        float a3 = g3 + adv; a3 = a3 > 0.f ? a3 : 0.2f * a3;
        float w0 = __expf(a0), w1 = __expf(a1), w2 = __expf(a2), w3 = __expf(a3);
        ax = fmaf(w0, h0.x, ax); ay = fmaf(w0, h0.y, ay);
        ax = fmaf(w1, h1v.x, ax); ay = fmaf(w1, h1v.y, ay);
        ax = fmaf(w2, h2v.x, ax); ay = fmaf(w2, h2v.y, ay);
        ax = fmaf(w3, h3.x, ax); ay = fmaf(w3, h3.y, ay);
        wsum += (w0 + w1) + (w2 + w3);
    }
    for (; e < e1; e++) {            // tail
        int s = __ldg(&d_col[e]);
        float al = __ldg(&d_as1[s * HEADS1 + hd]) + adv;
        al = al > 0.f ? al : 0.2f * al;
        float w = __expf(al);
        float2 hv = *(const float2*)(d_h1 + (size_t)s * HID + c2);
        ax = fmaf(w, hv.x, ax); ay = fmaf(w, hv.y, ay);
        wsum += w;
    }

    float inv = 1.0f / (wsum + 1e-16f);
    float vx = ax * inv + b1[c2];
    float vy = ay * inv + b1[c2 + 1];
    vx = vx > 0.f ? vx : expm1f(vx);           // elu
    vy = vy > 0.f ? vy : expm1f(vy);
    *(float2*)(d_hmid + (size_t)n * HID + c2) = make_float2(vx, vy);
}

// ---------------- layer 2 node stage: h2p = {hmid @ W2, as2}, ad2 ----------------
__global__ void k_l2node(const float* __restrict__ W2,
                         const float* __restrict__ a_src2,
                         const float* __restrict__ a_dst2) {
    __shared__ float sW[HID * OUT_CH];
    __shared__ float sa[OUT_CH], sd[OUT_CH];
    int t = threadIdx.x;
    if (t < HID * OUT_CH) sW[t] = W2[t];
    if (t < OUT_CH) { sa[t] = a_src2[t]; sd[t] = a_dst2[t]; }
    __syncthreads();
    int n = blockIdx.x * blockDim.x + t;
    if (n >= N_NODES) return;
    const float* hp = d_hmid + (size_t)n * HID;
    float o0 = 0.f, o1 = 0.f, o2 = 0.f;
    #pragma unroll
    for (int k = 0; k < HID; k += 4) {
        float4 v = *(const float4*)(hp + k);
        o0 += v.x * sW[k * 3 + 0] + v.y * sW[(k + 1) * 3 + 0] + v.z * sW[(k + 2) * 3 + 0] + v.w * sW[(k + 3) * 3 + 0];
        o1 += v.x * sW[k * 3 + 1] + v.y * sW[(k + 1) * 3 + 1] + v.z * sW[(k + 2) * 3 + 1] + v.w * sW[(k + 3) * 3 + 1];
        o2 += v.x * sW[k * 3 + 2] + v.y * sW[(k + 1) * 3 + 2] + v.z * sW[(k + 2) * 3 + 2] + v.w * sW[(k + 3) * 3 + 2];
    }
    float as = o0 * sa[0] + o1 * sa[1] + o2 * sa[2];
    d_h2p[n] = make_float4(o0, o1, o2, as);
    d_ad2[n] = o0 * sd[0] + o1 * sd[1] + o2 * sd[2];
}

// ---------------- GAT pull layer 2: warp per dst node, lane per edge ----------------
__global__ void __launch_bounds__(128) k_pull2(float* __restrict__ out,
                                               const float* __restrict__ b2) {
    int n = blockIdx.x * 4 + (threadIdx.x >> 5);
    if (n >= N_NODES) return;
    int lane = threadIdx.x & 31;
    int e0 = d_rowptr[n], e1 = d_rowptr[n + 1];
    float adv = d_ad2[n];
    float a0 = 0.f, a1 = 0.f, a2 = 0.f, wsum = 0.f;
    for (int e = e0 + lane; e < e1; e += 32) {
        int s = __ldg(&d_col[e]);
        float4 pk = *(const float4*)&d_h2p[s];   // {h2, as2}
        float al = pk.w + adv;
        al = al > 0.f ? al : 0.2f * al;
        float w = __expf(al);
        a0 = fmaf(w, pk.x, a0);
        a1 = fmaf(w, pk.y, a1);
        a2 = fmaf(w, pk.z, a2);
        wsum += w;
    }
    #pragma unroll
    for (int o = 16; o > 0; o >>= 1) {
        a0 += __shfl_xor_sync(0xffffffffu, a0, o);
        a1 += __shfl_xor_sync(0xffffffffu, a1, o);
        a2 += __shfl_xor_sync(0xffffffffu, a2, o);
        wsum += __shfl_xor_sync(0xffffffffu, wsum, o);
    }
    if (lane < 3) {
        float inv = 1.0f / (wsum + 1e-16f);
        float v = (lane == 0) ? a0 : ((lane == 1) ? a1 : a2);
        out[n * 3 + lane] = v * inv + b2[lane];
    }
}

// ---------------- launch ----------------
extern "C" void kernel_launch(void* const* d_in, const int* in_sizes, int n_in,
                              void* d_out, int out_size) {
    const float* x      = (const float*)d_in[0];
    const void*  ei     = d_in[1];
    const float* W1     = (const float*)d_in[2];
    const float* a_src1 = (const float*)d_in[3];
    const float* a_dst1 = (const float*)d_in[4];
    const float* b1     = (const float*)d_in[5];
    const float* W2     = (const float*)d_in[6];
    const float* a_src2 = (const float*)d_in[7];
    const float* a_dst2 = (const float*)d_in[8];
    const float* b2     = (const float*)d_in[9];
    float* out = (float*)d_out;

    // k_gemm1 kept at launch index 3 (ncu's profiled slot).
    k_detect<<<1, 256>>>((const int*)ei);
    k_init<<<(CNT_PAD + 255) / 256, 256>>>();
    k_hist<<<(E_REAL + 255) / 256, 256>>>(ei);
    k_gemm1<<<(N_NODES + 127) / 128, 256>>>(x, W1, a_src1, a_dst1);   // profiled
    k_scan_part<<<196, 256>>>();
    k_scan_top<<<1, 256>>>();
    k_scan_chunk<<<196, 512>>>();
    k_selfloop<<<(N_NODES + 255) / 256, 256>>>();
    k_scatter<<<(E_REAL + 255) / 256, 256>>>(ei);

    // Layer 1 edge phase
    k_pull1<<<(N_NODES + 3) / 4, 128>>>(b1);

    // Layer 2
    k_l2node<<<(N_NODES + 255) / 256, 256>>>(W2, a_src2, a_dst2);
    k_pull2<<<(N_NODES + 3) / 4, 128>>>(out, b2);
}

// round 8
// speedup vs baseline: 1.2837x; 1.2837x over previous
#include <cuda_runtime.h>
#include <cuda_bf16.h>
#include <cstdint>

#define N_NODES 100000
#define E_REAL  3200000
#define E_TOT   3300000
#define IN_CH   256
#define HID     64
#define HEADS1  8
#define OUT_CH  3
#define CNT_PAD 100352   // 196 * 512

typedef unsigned long long ull;

// ---------------- scratch (static device globals; no runtime alloc) ----------------
__device__ int   d_is64;
__device__ int   d_cnt[CNT_PAD];
__device__ int   d_rowptr[N_NODES + 1];
__device__ int   d_part[256];
__device__ __align__(16) int d_col[E_TOT];
__device__ __align__(16) float  d_h1[N_NODES * HID];
__device__ __align__(16) float  d_as1[N_NODES * HEADS1];
__device__ __align__(16) float  d_ad1[N_NODES * HEADS1];
__device__ __align__(16) float  d_hmid[N_NODES * HID];
__device__ __align__(16) float4 d_h2p[N_NODES];          // {h2[0..2], as2}
__device__ __align__(16) float  d_ad2[N_NODES];

// Decode edge endpoint i; which=0 -> src row, which=1 -> dst row.
__device__ __forceinline__ int edge_at(const void* ei, int which, int i) {
    if (d_is64) {
        const long long* p = (const long long*)ei;
        return (int)p[(size_t)which * E_REAL + i];
    } else {
        const int* p = (const int*)ei;
        return p[(size_t)which * E_REAL + i];
    }
}

// ---------------- dtype probe ----------------
__global__ void k_detect(const int* __restrict__ ei32) {
    __shared__ int nz;
    if (threadIdx.x == 0) nz = 0;
    __syncthreads();
    if (ei32[2 * threadIdx.x + 1] != 0) atomicOr(&nz, 1);
    __syncthreads();
    if (threadIdx.x == 0) d_is64 = (nz == 0) ? 1 : 0;
}

// ---------------- CSR build ----------------
__global__ void k_init() {
    int i = blockIdx.x * blockDim.x + threadIdx.x;
    if (i < CNT_PAD) d_cnt[i] = (i < N_NODES) ? 1 : 0;
}

__global__ void k_hist(const void* __restrict__ ei) {
    int i = blockIdx.x * blockDim.x + threadIdx.x;
    if (i < E_REAL) {
        int d = edge_at(ei, 1, i);
        if ((unsigned)d < N_NODES) atomicAdd(&d_cnt[d], 1);
    }
}

__global__ void k_scan_part() {
    __shared__ int s[256];
    int b = blockIdx.x, t = threadIdx.x;
    int i0 = b * 512 + t;
    int v = d_cnt[i0] + d_cnt[i0 + 256];
    s[t] = v; __syncthreads();
    for (int off = 128; off > 0; off >>= 1) {
        if (t < off) s[t] += s[t + off];
        __syncthreads();
    }
    if (t == 0) d_part[b] = s[0];
}

__global__ void k_scan_top() {
    __shared__ int s[256];
    int t = threadIdx.x;
    int v = (t < 196) ? d_part[t] : 0;
    s[t] = v; __syncthreads();
    for (int off = 1; off < 256; off <<= 1) {
        int x = (t >= off) ? s[t - off] : 0;
        __syncthreads();
        s[t] += x;
        __syncthreads();
    }
    if (t < 196) d_part[t] = s[t] - v;
}

__global__ void k_scan_chunk() {
    __shared__ int s[512];
    int b = blockIdx.x, t = threadIdx.x;
    int i = b * 512 + t;
    int v = d_cnt[i];
    s[t] = v; __syncthreads();
    for (int off = 1; off < 512; off <<= 1) {
        int x = (t >= off) ? s[t - off] : 0;
        __syncthreads();
        s[t] += x;
        __syncthreads();
    }
    if (i <= N_NODES) d_rowptr[i] = d_part[b] + s[t] - v;
}

__global__ void k_selfloop() {
    int i = blockIdx.x * blockDim.x + threadIdx.x;
    if (i < N_NODES) {
        int p = d_rowptr[i];
        d_col[p] = i;
        d_cnt[i] = p + 1;
    }
}

__global__ void k_scatter(const void* __restrict__ ei) {
    int i = blockIdx.x * blockDim.x + threadIdx.x;
    if (i < E_REAL) {
        int s = edge_at(ei, 0, i);
        int d = edge_at(ei, 1, i);
        if ((unsigned)d < N_NODES && (unsigned)s < N_NODES) {
            int p = atomicAdd(&d_cnt[d], 1);
            d_col[p] = s;
        }
    }
}

// ---------------- GEMM1: mma.sync bf16x3 (fp32-accurate) + fused alpha1 ----------------
// h1 = x @ W1 (100000x256 @ 256x64). Block 256 thr, tile 128 rows x 64 cols.
// K in 4 chunks of 64. smem: A_hi/A_lo [128][72] bf16, B_hi/B_lo [64][72] bf16
// (stride 72 elems = 144 B -> conflict-free fragment loads).
// Warp w: rows w*16..+15. 8 n-tiles of m16n8k16; D += Ah*Bh + Ah*Bl + Al*Bh.
#define KC      64
#define LDE     72                  // padded row stride, elements
#define LDB     144                 // bytes
static constexpr int A_HI = 0;
static constexpr int A_LO = 128 * LDB;           // 18432
static constexpr int B_HI = 2 * 128 * LDB;       // 36864
static constexpr int B_LO = B_HI + 64 * LDB;     // 46080
static constexpr int GEMM_SMEM = B_LO + 64 * LDB;// 55296

__device__ __forceinline__ void mma_bf16(float* c, const uint32_t* a, const uint32_t* b) {
    asm volatile(
        "mma.sync.aligned.m16n8k16.row.col.f32.bf16.bf16.f32 "
        "{%0,%1,%2,%3}, {%4,%5,%6,%7}, {%8,%9}, {%0,%1,%2,%3};"
        : "+f"(c[0]), "+f"(c[1]), "+f"(c[2]), "+f"(c[3])
        : "r"(a[0]), "r"(a[1]), "r"(a[2]), "r"(a[3]), "r"(b[0]), "r"(b[1]));
}

__device__ __forceinline__ void split4(float4 v, uint32_t& h0, uint32_t& h1,
                                       uint32_t& l0, uint32_t& l1) {
    __nv_bfloat16 a = __float2bfloat16_rn(v.x), b = __float2bfloat16_rn(v.y);
    __nv_bfloat16 c = __float2bfloat16_rn(v.z), d = __float2bfloat16_rn(v.w);
    __nv_bfloat16 e = __float2bfloat16_rn(v.x - __bfloat162float(a));
    __nv_bfloat16 f = __float2bfloat16_rn(v.y - __bfloat162float(b));
    __nv_bfloat16 g = __float2bfloat16_rn(v.z - __bfloat162float(c));
    __nv_bfloat16 h = __float2bfloat16_rn(v.w - __bfloat162float(d));
    h0 = (uint32_t)*(unsigned short*)&a | ((uint32_t)*(unsigned short*)&b << 16);
    h1 = (uint32_t)*(unsigned short*)&c | ((uint32_t)*(unsigned short*)&d << 16);
    l0 = (uint32_t)*(unsigned short*)&e | ((uint32_t)*(unsigned short*)&f << 16);
    l1 = (uint32_t)*(unsigned short*)&g | ((uint32_t)*(unsigned short*)&h << 16);
}

__global__ void __launch_bounds__(256) k_gemm1(const float* __restrict__ x,
                                               const float* __restrict__ W,
                                               const float* __restrict__ a_src,
                                               const float* __restrict__ a_dst) {
    extern __shared__ __align__(16) char sm[];
    int t = threadIdx.x, wid = t >> 5, lane = t & 31;
    int g = lane >> 2, tq = lane & 3;        // group row, thread-in-group
    int row0 = blockIdx.x * 128;
    int wrow = wid * 16;
    float acc[8][4];
    #pragma unroll
    for (int i = 0; i < 8; i++)
        #pragma unroll
        for (int j = 0; j < 4; j++) acc[i][j] = 0.f;

    for (int kc = 0; kc < 4; kc++) {
        int k0 = kc * KC;
        if (kc) __syncthreads();             // all frag LDS of prev chunk consumed
        // A: 128 rows x 16 float4 -> hi/lo, 8 float4 per thread
        #pragma unroll
        for (int j = 0; j < 8; j++) {
            int f4 = t + 256 * j;
            int r = f4 >> 4, c4 = f4 & 15;
            int grow = row0 + r;
            float4 v = (grow < N_NODES)
                ? *(const float4*)(x + (size_t)grow * IN_CH + k0 + c4 * 4)
                : make_float4(0.f, 0.f, 0.f, 0.f);
            uint32_t h0, h1, l0, l1;
            split4(v, h0, h1, l0, l1);
            int off = r * LDB + c4 * 8;
            *(ull*)(sm + A_HI + off) = (ull)h0 | ((ull)h1 << 32);
            *(ull*)(sm + A_LO + off) = (ull)l0 | ((ull)l1 << 32);
        }
        // B: sB[n][k] = W[(k0+k)*64 + n], 64x64, 16 elems per thread
        #pragma unroll
        for (int j = 0; j < 16; j++) {
            int idx = t + 256 * j;
            int n = idx & 63, k = idx >> 6;
            float v = __ldg(W + (size_t)(k0 + k) * HID + n);
            __nv_bfloat16 h = __float2bfloat16_rn(v);
            __nv_bfloat16 l = __float2bfloat16_rn(v - __bfloat162float(h));
            int off = n * LDB + k * 2;
            *(unsigned short*)(sm + B_HI + off) = *(unsigned short*)&h;
            *(unsigned short*)(sm + B_LO + off) = *(unsigned short*)&l;
        }
        __syncthreads();

        #pragma unroll
        for (int ks = 0; ks < 4; ks++) {
            // A fragments: reg0 (g, t2) | reg1 (g+8, t2) | reg2 (g, t2+8) | reg3 (g+8, t2+8)
            int abase = (wrow + g) * LDB + ks * 32 + tq * 4;
            uint32_t ah[4], al[4];
            ah[0] = *(const uint32_t*)(sm + A_HI + abase);
            ah[1] = *(const uint32_t*)(sm + A_HI + abase + 8 * LDB);
            ah[2] = *(const uint32_t*)(sm + A_HI + abase + 16);
            ah[3] = *(const uint32_t*)(sm + A_HI + abase + 8 * LDB + 16);
            al[0] = *(const uint32_t*)(sm + A_LO + abase);
            al[1] = *(const uint32_t*)(sm + A_LO + abase + 8 * LDB);
            al[2] = *(const uint32_t*)(sm + A_LO + abase + 16);
            al[3] = *(const uint32_t*)(sm + A_LO + abase + 8 * LDB + 16);
            #pragma unroll
            for (int nt = 0; nt < 8; nt++) {
                int bbase = (nt * 8 + g) * LDB + ks * 32 + tq * 4;
                uint32_t bh[2], bl[2];
                bh[0] = *(const uint32_t*)(sm + B_HI + bbase);
                bh[1] = *(const uint32_t*)(sm + B_HI + bbase + 16);
                bl[0] = *(const uint32_t*)(sm + B_LO + bbase);
                bl[1] = *(const uint32_t*)(sm + B_LO + bbase + 16);
                mma_bf16(acc[nt], ah, bh);
                mma_bf16(acc[nt], ah, bl);
                mma_bf16(acc[nt], al, bh);
            }
        }
    }

    // Epilogue. Thread holds cols nt*8 + tq*2 + {0,1} for rows (wrow+g) [d0,d1]
    // and (wrow+g+8) [d2,d3]. Head h == nt.
    int rA = row0 + wrow + g;
    int rB = rA + 8;
    if (rA < N_NODES) {
        #pragma unroll
        for (int nt = 0; nt < 8; nt++)
            *(float2*)(d_h1 + (size_t)rA * HID + nt * 8 + tq * 2) =
                make_float2(acc[nt][0], acc[nt][1]);
    }
    if (rB < N_NODES) {
        #pragma unroll
        for (int nt = 0; nt < 8; nt++)
            *(float2*)(d_h1 + (size_t)rB * HID + nt * 8 + tq * 2) =
                make_float2(acc[nt][2], acc[nt][3]);
    }
    // Fused alphas: quad-reduce per head
    #pragma unroll
    for (int nt = 0; nt < 8; nt++) {
        float s0 = __ldg(a_src + nt * 8 + tq * 2), s1 = __ldg(a_src + nt * 8 + tq * 2 + 1);
        float d0 = __ldg(a_dst + nt * 8 + tq * 2), d1 = __ldg(a_dst + nt * 8 + tq * 2 + 1);
        float pa = acc[nt][0] * s0 + acc[nt][1] * s1;   // row rA, src
        float pb = acc[nt][2] * s0 + acc[nt][3] * s1;   // row rB, src
        float qa = acc[nt][0] * d0 + acc[nt][1] * d1;   // row rA, dst
        float qb = acc[nt][2] * d0 + acc[nt][3] * d1;   // row rB, dst
        #pragma unroll
        for (int o = 1; o < 4; o <<= 1) {
            pa += __shfl_xor_sync(0xffffffffu, pa, o);
            pb += __shfl_xor_sync(0xffffffffu, pb, o);
            qa += __shfl_xor_sync(0xffffffffu, qa, o);
            qb += __shfl_xor_sync(0xffffffffu, qb, o);
        }
        if (tq == (nt & 3)) {
            if (rA < N_NODES) { d_as1[rA * HEADS1 + nt] = pa; d_ad1[rA * HEADS1 + nt] = qa; }
            if (rB < N_NODES) { d_as1[rB * HEADS1 + nt] = pb; d_ad1[rB * HEADS1 + nt] = qb; }
        }
    }
}

// ---------------- GAT pull layer 1: warp per dst node, lane owns 2 channels ----------
__global__ void __launch_bounds__(128) k_pull1(const float* __restrict__ b1) {
    int n = blockIdx.x * 4 + (threadIdx.x >> 5);
    if (n >= N_NODES) return;
    int lane = threadIdx.x & 31;
    int c2 = lane * 2;
    int hd = lane >> 2;
    float adv = d_ad1[n * HEADS1 + hd];
    int e0 = d_rowptr[n], e1 = d_rowptr[n + 1];
    float ax = 0.f, ay = 0.f, wsum = 0.f;

    int e = e0;
    int ehead = (e0 + 3) & ~3;
    if (ehead > e1) ehead = e1;
    for (; e < ehead; e++) {
        int s = __ldg(&d_col[e]);
        float al = __ldg(&d_as1[s * HEADS1 + hd]) + adv;
        al = al > 0.f ? al : 0.2f * al;
        float w = __expf(al);
        float2 hv = *(const float2*)(d_h1 + (size_t)s * HID + c2);
        ax = fmaf(w, hv.x, ax); ay = fmaf(w, hv.y, ay);
        wsum += w;
    }
    for (; e + 4 <= e1; e += 4) {
        int4 c4 = *(const int4*)&d_col[e];
        float g0 = __ldg(&d_as1[c4.x * HEADS1 + hd]);
        float g1 = __ldg(&d_as1[c4.y * HEADS1 + hd]);
        float g2 = __ldg(&d_as1[c4.z * HEADS1 + hd]);
        float g3 = __ldg(&d_as1[c4.w * HEADS1 + hd]);
        float2 h0 = *(const float2*)(d_h1 + (size_t)c4.x * HID + c2);
        float2 h1v = *(const float2*)(d_h1 + (size_t)c4.y * HID + c2);
        float2 h2v = *(const float2*)(d_h1 + (size_t)c4.z * HID + c2);
        float2 h3 = *(const float2*)(d_h1 + (size_t)c4.w * HID + c2);
        float a0 = g0 + adv; a0 = a0 > 0.f ? a0 : 0.2f * a0;
        float a1 = g1 + adv; a1 = a1 > 0.f ? a1 : 0.2f * a1;
        float a2 = g2 + adv; a2 = a2 > 0.f ? a2 : 0.2f * a2;
        float a3 = g3 + adv; a3 = a3 > 0.f ? a3 : 0.2f * a3;
        float w0 = __expf(a0), w1 = __expf(a1), w2 = __expf(a2), w3 = __expf(a3);
        ax = fmaf(w0, h0.x, ax); ay = fmaf(w0, h0.y, ay);
        ax = fmaf(w1, h1v.x, ax); ay = fmaf(w1, h1v.y, ay);
        ax = fmaf(w2, h2v.x, ax); ay = fmaf(w2, h2v.y, ay);
        ax = fmaf(w3, h3.x, ax); ay = fmaf(w3, h3.y, ay);
        wsum += (w0 + w1) + (w2 + w3);
    }
    for (; e < e1; e++) {
        int s = __ldg(&d_col[e]);
        float al = __ldg(&d_as1[s * HEADS1 + hd]) + adv;
        al = al > 0.f ? al : 0.2f * al;
        float w = __expf(al);
        float2 hv = *(const float2*)(d_h1 + (size_t)s * HID + c2);
        ax = fmaf(w, hv.x, ax); ay = fmaf(w, hv.y, ay);
        wsum += w;
    }

    float inv = 1.0f / (wsum + 1e-16f);
    float vx = ax * inv + b1[c2];
    float vy = ay * inv + b1[c2 + 1];
    vx = vx > 0.f ? vx : expm1f(vx);
    vy = vy > 0.f ? vy : expm1f(vy);
    *(float2*)(d_hmid + (size_t)n * HID + c2) = make_float2(vx, vy);
}

// ---------------- layer 2 node stage ----------------
__global__ void k_l2node(const float* __restrict__ W2,
                         const float* __restrict__ a_src2,
                         const float* __restrict__ a_dst2) {
    __shared__ float sW[HID * OUT_CH];
    __shared__ float sa[OUT_CH], sd[OUT_CH];
    int t = threadIdx.x;
    if (t < HID * OUT_CH) sW[t] = W2[t];
    if (t < OUT_CH) { sa[t] = a_src2[t]; sd[t] = a_dst2[t]; }
    __syncthreads();
    int n = blockIdx.x * blockDim.x + t;
    if (n >= N_NODES) return;
    const float* hp = d_hmid + (size_t)n * HID;
    float o0 = 0.f, o1 = 0.f, o2 = 0.f;
    #pragma unroll
    for (int k = 0; k < HID; k += 4) {
        float4 v = *(const float4*)(hp + k);
        o0 += v.x * sW[k * 3 + 0] + v.y * sW[(k + 1) * 3 + 0] + v.z * sW[(k + 2) * 3 + 0] + v.w * sW[(k + 3) * 3 + 0];
        o1 += v.x * sW[k * 3 + 1] + v.y * sW[(k + 1) * 3 + 1] + v.z * sW[(k + 2) * 3 + 1] + v.w * sW[(k + 3) * 3 + 1];
        o2 += v.x * sW[k * 3 + 2] + v.y * sW[(k + 1) * 3 + 2] + v.z * sW[(k + 2) * 3 + 2] + v.w * sW[(k + 3) * 3 + 2];
    }
    float as = o0 * sa[0] + o1 * sa[1] + o2 * sa[2];
    d_h2p[n] = make_float4(o0, o1, o2, as);
    d_ad2[n] = o0 * sd[0] + o1 * sd[1] + o2 * sd[2];
}

// ---------------- GAT pull layer 2 ----------------
__global__ void __launch_bounds__(128) k_pull2(float* __restrict__ out,
                                               const float* __restrict__ b2) {
    int n = blockIdx.x * 4 + (threadIdx.x >> 5);
    if (n >= N_NODES) return;
    int lane = threadIdx.x & 31;
    int e0 = d_rowptr[n], e1 = d_rowptr[n + 1];
    float adv = d_ad2[n];
    float a0 = 0.f, a1 = 0.f, a2 = 0.f, wsum = 0.f;
    for (int e = e0 + lane; e < e1; e += 32) {
        int s = __ldg(&d_col[e]);
        float4 pk = *(const float4*)&d_h2p[s];
        float al = pk.w + adv;
        al = al > 0.f ? al : 0.2f * al;
        float w = __expf(al);
        a0 = fmaf(w, pk.x, a0);
        a1 = fmaf(w, pk.y, a1);
        a2 = fmaf(w, pk.z, a2);
        wsum += w;
    }
    #pragma unroll
    for (int o = 16; o > 0; o >>= 1) {
        a0 += __shfl_xor_sync(0xffffffffu, a0, o);
        a1 += __shfl_xor_sync(0xffffffffu, a1, o);
        a2 += __shfl_xor_sync(0xffffffffu, a2, o);
        wsum += __shfl_xor_sync(0xffffffffu, wsum, o);
    }
    if (lane < 3) {
        float inv = 1.0f / (wsum + 1e-16f);
        float v = (lane == 0) ? a0 : ((lane == 1) ? a1 : a2);
        out[n * 3 + lane] = v * inv + b2[lane];
    }
}

// ---------------- launch ----------------
extern "C" void kernel_launch(void* const* d_in, const int* in_sizes, int n_in,
                              void* d_out, int out_size) {
    const float* x      = (const float*)d_in[0];
    const void*  ei     = d_in[1];
    const float* W1     = (const float*)d_in[2];
    const float* a_src1 = (const float*)d_in[3];
    const float* a_dst1 = (const float*)d_in[4];
    const float* b1     = (const float*)d_in[5];
    const float* W2     = (const float*)d_in[6];
    const float* a_src2 = (const float*)d_in[7];
    const float* a_dst2 = (const float*)d_in[8];
    const float* b2     = (const float*)d_in[9];
    float* out = (float*)d_out;

    cudaFuncSetAttribute(k_gemm1, cudaFuncAttributeMaxDynamicSharedMemorySize, GEMM_SMEM);

    // k_gemm1 kept at launch index 3 (ncu's profiled slot).
    k_detect<<<1, 256>>>((const int*)ei);
    k_init<<<(CNT_PAD + 255) / 256, 256>>>();
    k_hist<<<(E_REAL + 255) / 256, 256>>>(ei);
    k_gemm1<<<(N_NODES + 127) / 128, 256, GEMM_SMEM>>>(x, W1, a_src1, a_dst1);  // profiled
    k_scan_part<<<196, 256>>>();
    k_scan_top<<<1, 256>>>();
    k_scan_chunk<<<196, 512>>>();
    k_selfloop<<<(N_NODES + 255) / 256, 256>>>();
    k_scatter<<<(E_REAL + 255) / 256, 256>>>(ei);

    // Layer 1 edge phase
    k_pull1<<<(N_NODES + 3) / 4, 128>>>(b1);

    // Layer 2
    k_l2node<<<(N_NODES + 255) / 256, 256>>>(W2, a_src2, a_dst2);
    k_pull2<<<(N_NODES + 3) / 4, 128>>>(out, b2);
}

// round 9
// speedup vs baseline: 1.3905x; 1.0833x over previous
#include <cuda_runtime.h>
#include <cuda_bf16.h>
#include <cstdint>

#define N_NODES 100000
#define E_REAL  3200000
#define E_TOT   3300000
#define IN_CH   256
#define HID     64
#define HEADS1  8
#define OUT_CH  3
#define CNT_PAD 100352   // 196 * 512

typedef unsigned long long ull;

// ---------------- scratch (static device globals; no runtime alloc) ----------------
__device__ int   d_is64;
__device__ int   d_cnt[CNT_PAD];
__device__ int   d_rowptr[N_NODES + 1];
__device__ int   d_part[256];
__device__ __align__(16) int d_col[E_TOT];
__device__ __align__(16) float  d_h1[N_NODES * HID];
__device__ __align__(16) float  d_as1[N_NODES * HEADS1];
__device__ __align__(16) float  d_ad1[N_NODES * HEADS1];
__device__ __align__(16) float4 d_h2p[N_NODES];          // {h2[0..2], as2}
__device__ __align__(16) float  d_ad2[N_NODES];

// Decode edge endpoint i; which=0 -> src row, which=1 -> dst row.
__device__ __forceinline__ int edge_at(const void* ei, int which, int i) {
    if (d_is64) {
        const long long* p = (const long long*)ei;
        return (int)p[(size_t)which * E_REAL + i];
    } else {
        const int* p = (const int*)ei;
        return p[(size_t)which * E_REAL + i];
    }
}

// ---------------- dtype probe ----------------
__global__ void k_detect(const int* __restrict__ ei32) {
    __shared__ int nz;
    if (threadIdx.x == 0) nz = 0;
    __syncthreads();
    if (ei32[2 * threadIdx.x + 1] != 0) atomicOr(&nz, 1);
    __syncthreads();
    if (threadIdx.x == 0) d_is64 = (nz == 0) ? 1 : 0;
}

// ---------------- CSR build ----------------
__global__ void k_init() {
    int i = blockIdx.x * blockDim.x + threadIdx.x;
    if (i < CNT_PAD) d_cnt[i] = (i < N_NODES) ? 1 : 0;
}

__global__ void k_hist(const void* __restrict__ ei) {
    int i = blockIdx.x * blockDim.x + threadIdx.x;
    if (i < E_REAL) {
        int d = edge_at(ei, 1, i);
        if ((unsigned)d < N_NODES) atomicAdd(&d_cnt[d], 1);
    }
}

__global__ void k_scan_part() {
    __shared__ int s[256];
    int b = blockIdx.x, t = threadIdx.x;
    int i0 = b * 512 + t;
    int v = d_cnt[i0] + d_cnt[i0 + 256];
    s[t] = v; __syncthreads();
    for (int off = 128; off > 0; off >>= 1) {
        if (t < off) s[t] += s[t + off];
        __syncthreads();
    }
    if (t == 0) d_part[b] = s[0];
}

__global__ void k_scan_top() {
    __shared__ int s[256];
    int t = threadIdx.x;
    int v = (t < 196) ? d_part[t] : 0;
    s[t] = v; __syncthreads();
    for (int off = 1; off < 256; off <<= 1) {
        int x = (t >= off) ? s[t - off] : 0;
        __syncthreads();
        s[t] += x;
        __syncthreads();
    }
    if (t < 196) d_part[t] = s[t] - v;
}

__global__ void k_scan_chunk() {
    __shared__ int s[512];
    int b = blockIdx.x, t = threadIdx.x;
    int i = b * 512 + t;
    int v = d_cnt[i];
    s[t] = v; __syncthreads();
    for (int off = 1; off < 512; off <<= 1) {
        int x = (t >= off) ? s[t - off] : 0;
        __syncthreads();
        s[t] += x;
        __syncthreads();
    }
    if (i <= N_NODES) d_rowptr[i] = d_part[b] + s[t] - v;
}

__global__ void k_selfloop() {
    int i = blockIdx.x * blockDim.x + threadIdx.x;
    if (i < N_NODES) {
        int p = d_rowptr[i];
        d_col[p] = i;
        d_cnt[i] = p + 1;
    }
}

__global__ void k_scatter(const void* __restrict__ ei) {
    int i = blockIdx.x * blockDim.x + threadIdx.x;
    if (i < E_REAL) {
        int s = edge_at(ei, 0, i);
        int d = edge_at(ei, 1, i);
        if ((unsigned)d < N_NODES && (unsigned)s < N_NODES) {
            int p = atomicAdd(&d_cnt[d], 1);
            d_col[p] = s;
        }
    }
}

// ---------------- GEMM1: mma.sync bf16x3 (fp32-accurate) + fused alpha1 ----------------
#define KC      64
#define LDB     144                 // padded row stride, bytes (72 bf16)
static constexpr int A_HI = 0;
static constexpr int A_LO = 128 * LDB;           // 18432
static constexpr int B_HI = 2 * 128 * LDB;       // 36864
static constexpr int B_LO = B_HI + 64 * LDB;     // 46080
static constexpr int GEMM_SMEM = B_LO + 64 * LDB;// 55296

__device__ __forceinline__ void mma_bf16(float* c, const uint32_t* a, const uint32_t* b) {
    asm volatile(
        "mma.sync.aligned.m16n8k16.row.col.f32.bf16.bf16.f32 "
        "{%0,%1,%2,%3}, {%4,%5,%6,%7}, {%8,%9}, {%0,%1,%2,%3};"
        : "+f"(c[0]), "+f"(c[1]), "+f"(c[2]), "+f"(c[3])
        : "r"(a[0]), "r"(a[1]), "r"(a[2]), "r"(a[3]), "r"(b[0]), "r"(b[1]));
}

__device__ __forceinline__ void split4(float4 v, uint32_t& h0, uint32_t& h1,
                                       uint32_t& l0, uint32_t& l1) {
    __nv_bfloat16 a = __float2bfloat16_rn(v.x), b = __float2bfloat16_rn(v.y);
    __nv_bfloat16 c = __float2bfloat16_rn(v.z), d = __float2bfloat16_rn(v.w);
    __nv_bfloat16 e = __float2bfloat16_rn(v.x - __bfloat162float(a));
    __nv_bfloat16 f = __float2bfloat16_rn(v.y - __bfloat162float(b));
    __nv_bfloat16 g = __float2bfloat16_rn(v.z - __bfloat162float(c));
    __nv_bfloat16 h = __float2bfloat16_rn(v.w - __bfloat162float(d));
    h0 = (uint32_t)*(unsigned short*)&a | ((uint32_t)*(unsigned short*)&b << 16);
    h1 = (uint32_t)*(unsigned short*)&c | ((uint32_t)*(unsigned short*)&d << 16);
    l0 = (uint32_t)*(unsigned short*)&e | ((uint32_t)*(unsigned short*)&f << 16);
    l1 = (uint32_t)*(unsigned short*)&g | ((uint32_t)*(unsigned short*)&h << 16);
}

__global__ void __launch_bounds__(256) k_gemm1(const float* __restrict__ x,
                                               const float* __restrict__ W,
                                               const float* __restrict__ a_src,
                                               const float* __restrict__ a_dst) {
    extern __shared__ __align__(16) char sm[];
    int t = threadIdx.x, wid = t >> 5, lane = t & 31;
    int g = lane >> 2, tq = lane & 3;
    int row0 = blockIdx.x * 128;
    int wrow = wid * 16;
    float acc[8][4];
    #pragma unroll
    for (int i = 0; i < 8; i++)
        #pragma unroll
        for (int j = 0; j < 4; j++) acc[i][j] = 0.f;

    for (int kc = 0; kc < 4; kc++) {
        int k0 = kc * KC;
        if (kc) __syncthreads();
        #pragma unroll
        for (int j = 0; j < 8; j++) {
            int f4 = t + 256 * j;
            int r = f4 >> 4, c4 = f4 & 15;
            int grow = row0 + r;
            float4 v = (grow < N_NODES)
                ? *(const float4*)(x + (size_t)grow * IN_CH + k0 + c4 * 4)
                : make_float4(0.f, 0.f, 0.f, 0.f);
            uint32_t h0, h1, l0, l1;
            split4(v, h0, h1, l0, l1);
            int off = r * LDB + c4 * 8;
            *(ull*)(sm + A_HI + off) = (ull)h0 | ((ull)h1 << 32);
            *(ull*)(sm + A_LO + off) = (ull)l0 | ((ull)l1 << 32);
        }
        #pragma unroll
        for (int j = 0; j < 16; j++) {
            int idx = t + 256 * j;
            int n = idx & 63, k = idx >> 6;
            float v = __ldg(W + (size_t)(k0 + k) * HID + n);
            __nv_bfloat16 h = __float2bfloat16_rn(v);
            __nv_bfloat16 l = __float2bfloat16_rn(v - __bfloat162float(h));
            int off = n * LDB + k * 2;
            *(unsigned short*)(sm + B_HI + off) = *(unsigned short*)&h;
            *(unsigned short*)(sm + B_LO + off) = *(unsigned short*)&l;
        }
        __syncthreads();

        #pragma unroll
        for (int ks = 0; ks < 4; ks++) {
            int abase = (wrow + g) * LDB + ks * 32 + tq * 4;
            uint32_t ah[4], al[4];
            ah[0] = *(const uint32_t*)(sm + A_HI + abase);
            ah[1] = *(const uint32_t*)(sm + A_HI + abase + 8 * LDB);
            ah[2] = *(const uint32_t*)(sm + A_HI + abase + 16);
            ah[3] = *(const uint32_t*)(sm + A_HI + abase + 8 * LDB + 16);
            al[0] = *(const uint32_t*)(sm + A_LO + abase);
            al[1] = *(const uint32_t*)(sm + A_LO + abase + 8 * LDB);
            al[2] = *(const uint32_t*)(sm + A_LO + abase + 16);
            al[3] = *(const uint32_t*)(sm + A_LO + abase + 8 * LDB + 16);
            #pragma unroll
            for (int nt = 0; nt < 8; nt++) {
                int bbase = (nt * 8 + g) * LDB + ks * 32 + tq * 4;
                uint32_t bh[2], bl[2];
                bh[0] = *(const uint32_t*)(sm + B_HI + bbase);
                bh[1] = *(const uint32_t*)(sm + B_HI + bbase + 16);
                bl[0] = *(const uint32_t*)(sm + B_LO + bbase);
                bl[1] = *(const uint32_t*)(sm + B_LO + bbase + 16);
                mma_bf16(acc[nt], ah, bh);
                mma_bf16(acc[nt], ah, bl);
                mma_bf16(acc[nt], al, bh);
            }
        }
    }

    int rA = row0 + wrow + g;
    int rB = rA + 8;
    if (rA < N_NODES) {
        #pragma unroll
        for (int nt = 0; nt < 8; nt++)
            *(float2*)(d_h1 + (size_t)rA * HID + nt * 8 + tq * 2) =
                make_float2(acc[nt][0], acc[nt][1]);
    }
    if (rB < N_NODES) {
        #pragma unroll
        for (int nt = 0; nt < 8; nt++)
            *(float2*)(d_h1 + (size_t)rB * HID + nt * 8 + tq * 2) =
                make_float2(acc[nt][2], acc[nt][3]);
    }
    #pragma unroll
    for (int nt = 0; nt < 8; nt++) {
        float s0 = __ldg(a_src + nt * 8 + tq * 2), s1 = __ldg(a_src + nt * 8 + tq * 2 + 1);
        float d0 = __ldg(a_dst + nt * 8 + tq * 2), d1 = __ldg(a_dst + nt * 8 + tq * 2 + 1);
        float pa = acc[nt][0] * s0 + acc[nt][1] * s1;
        float pb = acc[nt][2] * s0 + acc[nt][3] * s1;
        float qa = acc[nt][0] * d0 + acc[nt][1] * d1;
        float qb = acc[nt][2] * d0 + acc[nt][3] * d1;
        #pragma unroll
        for (int o = 1; o < 4; o <<= 1) {
            pa += __shfl_xor_sync(0xffffffffu, pa, o);
            pb += __shfl_xor_sync(0xffffffffu, pb, o);
            qa += __shfl_xor_sync(0xffffffffu, qa, o);
            qb += __shfl_xor_sync(0xffffffffu, qb, o);
        }
        if (tq == (nt & 3)) {
            if (rA < N_NODES) { d_as1[rA * HEADS1 + nt] = pa; d_ad1[rA * HEADS1 + nt] = qa; }
            if (rB < N_NODES) { d_as1[rB * HEADS1 + nt] = pb; d_ad1[rB * HEADS1 + nt] = qb; }
        }
    }
}

// ---------------- GAT pull layer 1 + FUSED layer-2 node stage -------------------------
// Warp per dst node, lane owns 2 channels. After softmax-normalize + bias + elu,
// the warp holds the full 64-ch hmid vector in registers; fold in hmid @ W2 via
// 3 warp reductions and emit {h2, as2} + ad2 directly (no hmid array, no l2node).
__global__ void __launch_bounds__(128) k_pull1(const float* __restrict__ b1,
                                               const float* __restrict__ W2,
                                               const float* __restrict__ a_src2,
                                               const float* __restrict__ a_dst2) {
    int n = blockIdx.x * 4 + (threadIdx.x >> 5);
    if (n >= N_NODES) return;
    int lane = threadIdx.x & 31;
    int c2 = lane * 2;
    int hd = lane >> 2;
    float adv = d_ad1[n * HEADS1 + hd];
    int e0 = d_rowptr[n], e1 = d_rowptr[n + 1];
    float ax = 0.f, ay = 0.f, wsum = 0.f;

    int e = e0;
    int ehead = (e0 + 3) & ~3;
    if (ehead > e1) ehead = e1;
    for (; e < ehead; e++) {
        int s = __ldg(&d_col[e]);
        float al = __ldg(&d_as1[s * HEADS1 + hd]) + adv;
        al = al > 0.f ? al : 0.2f * al;
        float w = __expf(al);
        float2 hv = *(const float2*)(d_h1 + (size_t)s * HID + c2);
        ax = fmaf(w, hv.x, ax); ay = fmaf(w, hv.y, ay);
        wsum += w;
    }
    for (; e + 4 <= e1; e += 4) {
        int4 c4 = *(const int4*)&d_col[e];
        float g0 = __ldg(&d_as1[c4.x * HEADS1 + hd]);
        float g1 = __ldg(&d_as1[c4.y * HEADS1 + hd]);
        float g2 = __ldg(&d_as1[c4.z * HEADS1 + hd]);
        float g3 = __ldg(&d_as1[c4.w * HEADS1 + hd]);
        float2 h0 = *(const float2*)(d_h1 + (size_t)c4.x * HID + c2);
        float2 h1v = *(const float2*)(d_h1 + (size_t)c4.y * HID + c2);
        float2 h2v = *(const float2*)(d_h1 + (size_t)c4.z * HID + c2);
        float2 h3 = *(const float2*)(d_h1 + (size_t)c4.w * HID + c2);
        float a0 = g0 + adv; a0 = a0 > 0.f ? a0 : 0.2f * a0;
        float a1 = g1 + adv; a1 = a1 > 0.f ? a1 : 0.2f * a1;
        float a2 = g2 + adv; a2 = a2 > 0.f ? a2 : 0.2f * a2;
        float a3 = g3 + adv; a3 = a3 > 0.f ? a3 : 0.2f * a3;
        float w0 = __expf(a0), w1 = __expf(a1), w2 = __expf(a2), w3 = __expf(a3);
        ax = fmaf(w0, h0.x, ax); ay = fmaf(w0, h0.y, ay);
        ax = fmaf(w1, h1v.x, ax); ay = fmaf(w1, h1v.y, ay);
        ax = fmaf(w2, h2v.x, ax); ay = fmaf(w2, h2v.y, ay);
        ax = fmaf(w3, h3.x, ax); ay = fmaf(w3, h3.y, ay);
        wsum += (w0 + w1) + (w2 + w3);
    }
    for (; e < e1; e++) {
        int s = __ldg(&d_col[e]);
        float al = __ldg(&d_as1[s * HEADS1 + hd]) + adv;
        al = al > 0.f ? al : 0.2f * al;
        float w = __expf(al);
        float2 hv = *(const float2*)(d_h1 + (size_t)s * HID + c2);
        ax = fmaf(w, hv.x, ax); ay = fmaf(w, hv.y, ay);
        wsum += w;
    }

    float inv = 1.0f / (wsum + 1e-16f);
    float vx = ax * inv + __ldg(b1 + c2);
    float vy = ay * inv + __ldg(b1 + c2 + 1);
    vx = vx > 0.f ? vx : expm1f(vx);
    vy = vy > 0.f ? vy : expm1f(vy);

    // fused l2node: o_j = sum_c hmid[c] * W2[c][j], via warp reduce
    float o0 = vx * __ldg(W2 + c2 * 3 + 0) + vy * __ldg(W2 + (c2 + 1) * 3 + 0);
    float o1 = vx * __ldg(W2 + c2 * 3 + 1) + vy * __ldg(W2 + (c2 + 1) * 3 + 1);
    float o2 = vx * __ldg(W2 + c2 * 3 + 2) + vy * __ldg(W2 + (c2 + 1) * 3 + 2);
    #pragma unroll
    for (int o = 16; o > 0; o >>= 1) {
        o0 += __shfl_xor_sync(0xffffffffu, o0, o);
        o1 += __shfl_xor_sync(0xffffffffu, o1, o);
        o2 += __shfl_xor_sync(0xffffffffu, o2, o);
    }
    if (lane == 0) {
        float as2 = o0 * __ldg(a_src2) + o1 * __ldg(a_src2 + 1) + o2 * __ldg(a_src2 + 2);
        float ad2 = o0 * __ldg(a_dst2) + o1 * __ldg(a_dst2 + 1) + o2 * __ldg(a_dst2 + 2);
        d_h2p[n] = make_float4(o0, o1, o2, as2);
        d_ad2[n] = ad2;
    }
}

// ---------------- GAT pull layer 2 ----------------
__global__ void __launch_bounds__(128) k_pull2(float* __restrict__ out,
                                               const float* __restrict__ b2) {
    int n = blockIdx.x * 4 + (threadIdx.x >> 5);
    if (n >= N_NODES) return;
    int lane = threadIdx.x & 31;
    int e0 = d_rowptr[n], e1 = d_rowptr[n + 1];
    float adv = d_ad2[n];
    float a0 = 0.f, a1 = 0.f, a2 = 0.f, wsum = 0.f;
    for (int e = e0 + lane; e < e1; e += 32) {
        int s = __ldg(&d_col[e]);
        float4 pk = *(const float4*)&d_h2p[s];
        float al = pk.w + adv;
        al = al > 0.f ? al : 0.2f * al;
        float w = __expf(al);
        a0 = fmaf(w, pk.x, a0);
        a1 = fmaf(w, pk.y, a1);
        a2 = fmaf(w, pk.z, a2);
        wsum += w;
    }
    #pragma unroll
    for (int o = 16; o > 0; o >>= 1) {
        a0 += __shfl_xor_sync(0xffffffffu, a0, o);
        a1 += __shfl_xor_sync(0xffffffffu, a1, o);
        a2 += __shfl_xor_sync(0xffffffffu, a2, o);
        wsum += __shfl_xor_sync(0xffffffffu, wsum, o);
    }
    if (lane < 3) {
        float inv = 1.0f / (wsum + 1e-16f);
        float v = (lane == 0) ? a0 : ((lane == 1) ? a1 : a2);
        out[n * 3 + lane] = v * inv + b2[lane];
    }
}

// ---------------- launch ----------------
extern "C" void kernel_launch(void* const* d_in, const int* in_sizes, int n_in,
                              void* d_out, int out_size) {
    const float* x      = (const float*)d_in[0];
    const void*  ei     = d_in[1];
    const float* W1     = (const float*)d_in[2];
    const float* a_src1 = (const float*)d_in[3];
    const float* a_dst1 = (const float*)d_in[4];
    const float* b1     = (const float*)d_in[5];
    const float* W2     = (const float*)d_in[6];
    const float* a_src2 = (const float*)d_in[7];
    const float* a_dst2 = (const float*)d_in[8];
    const float* b2     = (const float*)d_in[9];
    float* out = (float*)d_out;

    cudaFuncSetAttribute(k_gemm1, cudaFuncAttributeMaxDynamicSharedMemorySize, GEMM_SMEM);

    // Side stream for gemm1 (depends only on x/W1) to overlap with the CSR build.
    // Created once; fork/join via events so graph capture records both branches.
    static cudaStream_t s2 = nullptr;
    static cudaEvent_t evF = nullptr, evG = nullptr;
    if (!s2) {
        cudaStreamCreateWithFlags(&s2, cudaStreamNonBlocking);
        cudaEventCreateWithFlags(&evF, cudaEventDisableTiming);
        cudaEventCreateWithFlags(&evG, cudaEventDisableTiming);
    }

    // fork
    cudaEventRecord(evF, 0);
    cudaStreamWaitEvent(s2, evF, 0);

    // main stream: CSR build
    k_detect<<<1, 256>>>((const int*)ei);
    k_init<<<(CNT_PAD + 255) / 256, 256>>>();
    k_hist<<<(E_REAL + 255) / 256, 256>>>(ei);
    // side stream: gemm1 (launch index 3 -> ncu profiled slot)
    k_gemm1<<<(N_NODES + 127) / 128, 256, GEMM_SMEM, s2>>>(x, W1, a_src1, a_dst1);
    k_scan_part<<<196, 256>>>();
    k_scan_top<<<1, 256>>>();
    k_scan_chunk<<<196, 512>>>();
    k_selfloop<<<(N_NODES + 255) / 256, 256>>>();
    k_scatter<<<(E_REAL + 255) / 256, 256>>>(ei);

    // join: pull1 needs both CSR and gemm1
    cudaEventRecord(evG, s2);
    cudaStreamWaitEvent(0, evG, 0);

    k_pull1<<<(N_NODES + 3) / 4, 128>>>(b1, W2, a_src2, a_dst2);
    k_pull2<<<(N_NODES + 3) / 4, 128>>>(out, b2);
}